// round 11
// baseline (speedup 1.0000x reference)
#include <cuda_runtime.h>

#define GRID_N 25
#define NN 625
#define BATCH 512
#define RTOT (BATCH*NN)      // 320000 rows
#define FIN 66
#define DOUT 64
#define TILE 64              // rows per block
#define THREADS 256
#define NTILES (RTOT/TILE)   // 5000
#define WSTRIDE 68           // padded smem stride for W tile (bank-conflict-free)

typedef unsigned long long ull;

// Device scratch (no allocations allowed in kernel_launch)
__device__ float g_Wt[FIN*DOUT];   // W_fc transposed: [f][d]
__device__ float g_a1[RTOT];       // h . W_at[:64]  + b_at
__device__ float g_a2[RTOT];       // h . W_at[64:]

// ---- packed fp32x2 helpers (Blackwell 2x fp32 path; PTX-only per SASS_QUICKREF) ----
__device__ __forceinline__ ull pack2(float v){
    ull r; asm("mov.b64 %0, {%1,%2};" : "=l"(r) : "f"(v), "f"(v)); return r;
}
__device__ __forceinline__ ull pack2b(float x, float y){
    ull r; asm("mov.b64 %0, {%1,%2};" : "=l"(r) : "f"(x), "f"(y)); return r;
}
__device__ __forceinline__ void fma2(ull& d, ull a, ull b){
    asm("fma.rn.f32x2 %0, %1, %2, %0;" : "+l"(d) : "l"(a), "l"(b));
}
__device__ __forceinline__ float2 unpack2(ull v){
    float2 r; asm("mov.b64 {%0,%1}, %2;" : "=f"(r.x), "=f"(r.y) : "l"(v)); return r;
}

// ---- Kernel 0: transpose W_fc [64][66] -> g_Wt [66][64] (runs once, tiny) ----
__global__ void prep_kernel(const float* __restrict__ Wfc){
    int i = blockIdx.x*blockDim.x + threadIdx.x;
    if (i < FIN*DOUT){
        int d = i / FIN, f = i - d*FIN;
        g_Wt[f*DOUT + d] = Wfc[i];
    }
}

// ---- Kernel 1: fused GEMM h = x @ Wt + b, write h (== attn_vector), and
//      per-row attention dot products a1 = h.u + b_at, a2 = h.v ----
__global__ __launch_bounds__(THREADS, 4)
void gemm_kernel(const float* __restrict__ x,
                 const float* __restrict__ bfc,
                 const float* __restrict__ Wat,
                 const float* __restrict__ bat,
                 float* __restrict__ hout)
{
    __shared__ float sW[FIN*WSTRIDE];   // 17952 B
    __shared__ float sX[TILE*FIN];      // 16896 B

    const int tid  = threadIdx.x;
    const int tc   = tid & 7;           // output-column group (8 d's each)
    const int rl   = tid >> 3;          // row lane 0..31 (handles rows rl and rl+32)
    const int tile = blockIdx.x;

    // Stage W tile (transposed, padded stride -> conflict-free reads & writes)
    for (int i = tid; i < FIN*DOUT; i += THREADS){
        int f = i >> 6, d = i & 63;
        sW[f*WSTRIDE + d] = g_Wt[i];
    }
    // Stage x tile: 64 rows x 66 floats, contiguous region -> float4 copy
    {
        const float4* xg = (const float4*)(x + (size_t)tile*(TILE*FIN));
        float4* xs = (float4*)sX;
        for (int i = tid; i < (TILE*FIN)/4; i += THREADS) xs[i] = xg[i];
    }
    __syncthreads();

    // Init accumulators with the fc bias (folded; epilogue add removed)
    const float4 bv0 = ((const float4*)bfc)[tc*2];
    const float4 bv1 = ((const float4*)bfc)[tc*2+1];
    ull acc[2][4];
    acc[0][0] = pack2b(bv0.x, bv0.y);  acc[0][1] = pack2b(bv0.z, bv0.w);
    acc[0][2] = pack2b(bv1.x, bv1.y);  acc[0][3] = pack2b(bv1.z, bv1.w);
    #pragma unroll
    for (int j = 0; j < 4; j++) acc[1][j] = acc[0][j];

    const float* x0 = &sX[rl*FIN];
    const float* x1 = &sX[(rl+32)*FIN];
    const char*  wb = (const char*)&sW[tc*8];

    // Capped unroll: 3-deep pipelining window keeps live regs < 64 (no spills).
    #pragma unroll 3
    for (int f = 0; f < FIN; f++){
        ull xa = pack2(x0[f]);
        ull xb = pack2(x1[f]);
        const ulonglong2* wp = (const ulonglong2*)(wb + f*(WSTRIDE*4));
        ulonglong2 w01 = wp[0];     // d = tc*8 .. tc*8+3
        ulonglong2 w23 = wp[1];     // d = tc*8+4 .. tc*8+7
        fma2(acc[0][0], xa, w01.x); fma2(acc[0][1], xa, w01.y);
        fma2(acc[0][2], xa, w23.x); fma2(acc[0][3], xa, w23.y);
        fma2(acc[1][0], xb, w01.x); fma2(acc[1][1], xb, w01.y);
        fma2(acc[1][2], xb, w23.x); fma2(acc[1][3], xb, w23.y);
    }

    // Epilogue: write h, fused attention dots + 8-lane tree reduce
    const float4 u0  = ((const float4*)Wat)[tc*2];
    const float4 u1  = ((const float4*)Wat)[tc*2+1];
    const float4 v0  = ((const float4*)Wat)[16 + tc*2];
    const float4 v1  = ((const float4*)Wat)[16 + tc*2+1];
    const float  batv = bat[0];

    #pragma unroll
    for (int r = 0; r < 2; r++){
        float2 p0 = unpack2(acc[r][0]);
        float2 p1 = unpack2(acc[r][1]);
        float2 p2 = unpack2(acc[r][2]);
        float2 p3 = unpack2(acc[r][3]);

        int grow = tile*TILE + rl + r*32;
        float4* hp = (float4*)&hout[(size_t)grow*DOUT + tc*8];
        hp[0] = make_float4(p0.x, p0.y, p1.x, p1.y);
        hp[1] = make_float4(p2.x, p2.y, p3.x, p3.y);

        float pa1 = p0.x*u0.x + p0.y*u0.y + p1.x*u0.z + p1.y*u0.w
                  + p2.x*u1.x + p2.y*u1.y + p3.x*u1.z + p3.y*u1.w;
        float pa2 = p0.x*v0.x + p0.y*v0.y + p1.x*v0.z + p1.y*v0.w
                  + p2.x*v1.x + p2.y*v1.y + p3.x*v1.z + p3.y*v1.w;
        #pragma unroll
        for (int o = 4; o; o >>= 1){
            pa1 += __shfl_down_sync(0xffffffffu, pa1, o, 8);
            pa2 += __shfl_down_sync(0xffffffffu, pa2, o, 8);
        }
        if (tc == 0){
            g_a1[grow] = pa1 + batv;   // fold b_at here
            g_a2[grow] = pa2;
        }
    }
}

// ---- Kernel 2: 9-way gather + leaky_relu + softmax -> attn_weight ----
__global__ void attn_kernel(float* __restrict__ wout){
    int r = blockIdx.x*blockDim.x + threadIdx.x;
    if (r >= RTOT) return;
    int b  = r / NN;
    int n  = r - b*NN;
    int gr = n / GRID_N;
    int gc = n - gr*GRID_N;
    // reference clamps: row 0 shifted +1, row 24 shifted -1 (same for cols)
    int rb = gr + (gr == 0) - (gr == GRID_N-1);
    int cb = gc + (gc == 0) - (gc == GRID_N-1);

    float A = g_a1[r];
    const float* a2b = g_a2 + b*NN;

    float s[9];
    #pragma unroll
    for (int k = 0; k < 9; k++){
        int dr = k/3 - 1, dc = k%3 - 1;
        float v = A + a2b[(rb+dr)*GRID_N + (cb+dc)];
        s[k] = (v > 0.f) ? v : 0.01f*v;      // leaky_relu(0.01)
    }
    float m = s[0];
    #pragma unroll
    for (int k = 1; k < 9; k++) m = fmaxf(m, s[k]);
    float sum = 0.f;
    #pragma unroll
    for (int k = 0; k < 9; k++){ s[k] = __expf(s[k] - m); sum += s[k]; }
    float inv = 1.0f / sum;
    #pragma unroll
    for (int k = 0; k < 9; k++) wout[(size_t)r*9 + k] = s[k]*inv;
}

extern "C" void kernel_launch(void* const* d_in, const int* in_sizes, int n_in,
                              void* d_out, int out_size)
{
    const float* x   = (const float*)d_in[0];   // [512,625,66]
    const float* Wfc = (const float*)d_in[1];   // [64,66]
    const float* bfc = (const float*)d_in[2];   // [64]
    const float* Wat = (const float*)d_in[3];   // [1,128]
    const float* bat = (const float*)d_in[4];   // [1]
    float* out = (float*)d_out;
    // output layout: attn_vector [512,625,64] then attn_weight [512,625,9]
    float* hout = out;
    float* wout = out + (size_t)RTOT*DOUT;

    prep_kernel<<<(FIN*DOUT + 255)/256, 256>>>(Wfc);
    gemm_kernel<<<NTILES, THREADS>>>(x, bfc, Wat, bat, hout);
    attn_kernel<<<(RTOT + 255)/256, 256>>>(wout);
}

// round 12
// speedup vs baseline: 1.6688x; 1.6688x over previous
#include <cuda_runtime.h>

#define GRID_N 25
#define NN 625
#define BATCH 512
#define RTOT (BATCH*NN)      // 320000 rows
#define FIN 66
#define DOUT 64
#define TILE 128             // rows per block
#define THREADS 256
#define NTILES (RTOT/TILE)   // 2500

// Device scratch (no allocations allowed in kernel_launch)
__device__ float g_Wt[FIN*DOUT];   // W_fc transposed: [f][d], row f 16-float4s
__device__ float g_a1[RTOT];       // h . W_at[:64]  + b_at
__device__ float g_a2[RTOT];       // h . W_at[64:]

// ---- Kernel 0: transpose W_fc [64][66] -> g_Wt [66][64] (tiny) ----
__global__ void prep_kernel(const float* __restrict__ Wfc){
    int i = blockIdx.x*blockDim.x + threadIdx.x;
    if (i < FIN*DOUT){
        int d = i / FIN, f = i - d*FIN;
        g_Wt[f*DOUT + d] = Wfc[i];
    }
}

// ---- Kernel 1: fused GEMM h = x @ Wt + b (h == attn_vector), plus per-row
//      attention dots a1 = h.u + b_at, a2 = h.v.
//      Scalar FFMA, 4 rows x 8 cols per thread. W streamed from L1 (global),
//      x tile staged in smem (broadcast reads). ----
__global__ __launch_bounds__(THREADS)
void gemm_kernel(const float* __restrict__ x,
                 const float* __restrict__ bfc,
                 const float* __restrict__ Wat,
                 const float* __restrict__ bat,
                 float* __restrict__ hout)
{
    __shared__ float sX[TILE*FIN];      // 33792 B

    const int tid  = threadIdx.x;
    const int tc   = tid & 7;           // output-column group (8 d's)
    const int rl   = tid >> 3;          // row lane 0..31 (rows rl + 32k)
    const int tile = blockIdx.x;

    // Stage x tile: 128 rows x 66 floats contiguous -> float4 copy (2112 float4)
    {
        const float4* xg = (const float4*)(x + (size_t)tile*(TILE*FIN));
        float4* xs = (float4*)sX;
        #pragma unroll 2
        for (int i = tid; i < (TILE*FIN)/4; i += THREADS) xs[i] = xg[i];
    }
    __syncthreads();

    // Init accumulators with fc bias (folded)
    const float4 bv0 = ((const float4*)bfc)[tc*2];
    const float4 bv1 = ((const float4*)bfc)[tc*2+1];
    float acc[4][8];
    #pragma unroll
    for (int k = 0; k < 4; k++){
        acc[k][0]=bv0.x; acc[k][1]=bv0.y; acc[k][2]=bv0.z; acc[k][3]=bv0.w;
        acc[k][4]=bv1.x; acc[k][5]=bv1.y; acc[k][6]=bv1.z; acc[k][7]=bv1.w;
    }

    const float4* wp = ((const float4*)g_Wt) + tc*2;  // row f at wp[f*16], wp[f*16+1]
    const float*  xp = &sX[rl*FIN];

    #pragma unroll 3
    for (int f = 0; f < FIN; f++){
        float4 w0 = wp[f*16];
        float4 w1 = wp[f*16 + 1];
        float xv0 = xp[f];
        float xv1 = xp[f + 32*FIN];
        float xv2 = xp[f + 64*FIN];
        float xv3 = xp[f + 96*FIN];

        acc[0][0] += xv0*w0.x; acc[0][1] += xv0*w0.y; acc[0][2] += xv0*w0.z; acc[0][3] += xv0*w0.w;
        acc[0][4] += xv0*w1.x; acc[0][5] += xv0*w1.y; acc[0][6] += xv0*w1.z; acc[0][7] += xv0*w1.w;
        acc[1][0] += xv1*w0.x; acc[1][1] += xv1*w0.y; acc[1][2] += xv1*w0.z; acc[1][3] += xv1*w0.w;
        acc[1][4] += xv1*w1.x; acc[1][5] += xv1*w1.y; acc[1][6] += xv1*w1.z; acc[1][7] += xv1*w1.w;
        acc[2][0] += xv2*w0.x; acc[2][1] += xv2*w0.y; acc[2][2] += xv2*w0.z; acc[2][3] += xv2*w0.w;
        acc[2][4] += xv2*w1.x; acc[2][5] += xv2*w1.y; acc[2][6] += xv2*w1.z; acc[2][7] += xv2*w1.w;
        acc[3][0] += xv3*w0.x; acc[3][1] += xv3*w0.y; acc[3][2] += xv3*w0.z; acc[3][3] += xv3*w0.w;
        acc[3][4] += xv3*w1.x; acc[3][5] += xv3*w1.y; acc[3][6] += xv3*w1.z; acc[3][7] += xv3*w1.w;
    }

    // Epilogue: write h, fused attention dots + 8-lane tree reduce
    const float4 u0  = ((const float4*)Wat)[tc*2];
    const float4 u1  = ((const float4*)Wat)[tc*2+1];
    const float4 v0  = ((const float4*)Wat)[16 + tc*2];
    const float4 v1  = ((const float4*)Wat)[16 + tc*2+1];
    const float  batv = bat[0];

    #pragma unroll
    for (int k = 0; k < 4; k++){
        int grow = tile*TILE + rl + k*32;
        float4* hp = (float4*)&hout[(size_t)grow*DOUT + tc*8];
        hp[0] = make_float4(acc[k][0], acc[k][1], acc[k][2], acc[k][3]);
        hp[1] = make_float4(acc[k][4], acc[k][5], acc[k][6], acc[k][7]);

        float pa1 = acc[k][0]*u0.x + acc[k][1]*u0.y + acc[k][2]*u0.z + acc[k][3]*u0.w
                  + acc[k][4]*u1.x + acc[k][5]*u1.y + acc[k][6]*u1.z + acc[k][7]*u1.w;
        float pa2 = acc[k][0]*v0.x + acc[k][1]*v0.y + acc[k][2]*v0.z + acc[k][3]*v0.w
                  + acc[k][4]*v1.x + acc[k][5]*v1.y + acc[k][6]*v1.z + acc[k][7]*v1.w;
        #pragma unroll
        for (int o = 4; o; o >>= 1){
            pa1 += __shfl_down_sync(0xffffffffu, pa1, o, 8);
            pa2 += __shfl_down_sync(0xffffffffu, pa2, o, 8);
        }
        if (tc == 0){
            g_a1[grow] = pa1 + batv;   // fold b_at here
            g_a2[grow] = pa2;
        }
    }
}

// ---- Kernel 2: 9-way gather + leaky_relu + softmax -> attn_weight ----
__global__ void attn_kernel(float* __restrict__ wout){
    int r = blockIdx.x*blockDim.x + threadIdx.x;
    if (r >= RTOT) return;
    int b  = r / NN;
    int n  = r - b*NN;
    int gr = n / GRID_N;
    int gc = n - gr*GRID_N;
    // reference clamps: row 0 shifted +1, row 24 shifted -1 (same for cols)
    int rb = gr + (gr == 0) - (gr == GRID_N-1);
    int cb = gc + (gc == 0) - (gc == GRID_N-1);

    float A = g_a1[r];
    const float* a2b = g_a2 + b*NN;

    float s[9];
    #pragma unroll
    for (int k = 0; k < 9; k++){
        int dr = k/3 - 1, dc = k%3 - 1;
        float v = A + a2b[(rb+dr)*GRID_N + (cb+dc)];
        s[k] = (v > 0.f) ? v : 0.01f*v;      // leaky_relu(0.01)
    }
    float m = s[0];
    #pragma unroll
    for (int k = 1; k < 9; k++) m = fmaxf(m, s[k]);
    float sum = 0.f;
    #pragma unroll
    for (int k = 0; k < 9; k++){ s[k] = __expf(s[k] - m); sum += s[k]; }
    float inv = 1.0f / sum;
    #pragma unroll
    for (int k = 0; k < 9; k++) wout[(size_t)r*9 + k] = s[k]*inv;
}

extern "C" void kernel_launch(void* const* d_in, const int* in_sizes, int n_in,
                              void* d_out, int out_size)
{
    const float* x   = (const float*)d_in[0];   // [512,625,66]
    const float* Wfc = (const float*)d_in[1];   // [64,66]
    const float* bfc = (const float*)d_in[2];   // [64]
    const float* Wat = (const float*)d_in[3];   // [1,128]
    const float* bat = (const float*)d_in[4];   // [1]
    float* out = (float*)d_out;
    // output layout: attn_vector [512,625,64] then attn_weight [512,625,9]
    float* hout = out;
    float* wout = out + (size_t)RTOT*DOUT;

    prep_kernel<<<(FIN*DOUT + 255)/256, 256>>>(Wfc);
    gemm_kernel<<<NTILES, THREADS>>>(x, bfc, Wat, bat, hout);
    attn_kernel<<<(RTOT + 255)/256, 256>>>(wout);
}

// round 13
// speedup vs baseline: 1.6826x; 1.0083x over previous
#include <cuda_runtime.h>

#define GRID_N 25
#define NN 625
#define BATCH 512
#define RTOT (BATCH*NN)      // 320000 rows
#define FIN 66
#define DOUT 64
#define TILE 128             // rows per block
#define THREADS 256
#define NTILES (RTOT/TILE)   // 2500

// Device scratch (no allocations allowed in kernel_launch)
__device__ float g_Wt[FIN*DOUT];   // W_fc transposed: [f][d], row f 16-float4s
__device__ float g_a1[RTOT];       // h . W_at[:64]  + b_at
__device__ float g_a2[RTOT];       // h . W_at[64:]

// ---- Kernel 0: transpose W_fc [64][66] -> g_Wt [66][64] (tiny) ----
__global__ void prep_kernel(const float* __restrict__ Wfc){
    int i = blockIdx.x*blockDim.x + threadIdx.x;
    if (i < FIN*DOUT){
        int d = i / FIN, f = i - d*FIN;
        g_Wt[f*DOUT + d] = Wfc[i];
    }
}

// ---- Kernel 1: fused GEMM h = x @ Wt + b (h == attn_vector), plus per-row
//      attention dots a1 = h.u + b_at, a2 = h.v.
//      Scalar FFMA, 4 rows x 8 cols per thread. W streamed from L1 (global),
//      x tile staged in smem (broadcast reads). ----
__global__ __launch_bounds__(THREADS)
void gemm_kernel(const float* __restrict__ x,
                 const float* __restrict__ bfc,
                 const float* __restrict__ Wat,
                 const float* __restrict__ bat,
                 float* __restrict__ hout)
{
    __shared__ float sX[TILE*FIN];      // 33792 B

    const int tid  = threadIdx.x;
    const int tc   = tid & 7;           // output-column group (8 d's)
    const int rl   = tid >> 3;          // row lane 0..31 (rows rl + 32k)
    const int tile = blockIdx.x;

    // Stage x tile: 128 rows x 66 floats contiguous -> float4 copy (2112 float4)
    {
        const float4* xg = (const float4*)(x + (size_t)tile*(TILE*FIN));
        float4* xs = (float4*)sX;
        #pragma unroll 2
        for (int i = tid; i < (TILE*FIN)/4; i += THREADS) xs[i] = xg[i];
    }
    __syncthreads();

    // Init accumulators with fc bias (folded)
    const float4 bv0 = ((const float4*)bfc)[tc*2];
    const float4 bv1 = ((const float4*)bfc)[tc*2+1];
    float acc[4][8];
    #pragma unroll
    for (int k = 0; k < 4; k++){
        acc[k][0]=bv0.x; acc[k][1]=bv0.y; acc[k][2]=bv0.z; acc[k][3]=bv0.w;
        acc[k][4]=bv1.x; acc[k][5]=bv1.y; acc[k][6]=bv1.z; acc[k][7]=bv1.w;
    }

    const float4* wp = ((const float4*)g_Wt) + tc*2;  // row f at wp[f*16], wp[f*16+1]
    const float*  xp = &sX[rl*FIN];

    #pragma unroll 3
    for (int f = 0; f < FIN; f++){
        float4 w0 = wp[f*16];
        float4 w1 = wp[f*16 + 1];
        float xv0 = xp[f];
        float xv1 = xp[f + 32*FIN];
        float xv2 = xp[f + 64*FIN];
        float xv3 = xp[f + 96*FIN];

        acc[0][0] += xv0*w0.x; acc[0][1] += xv0*w0.y; acc[0][2] += xv0*w0.z; acc[0][3] += xv0*w0.w;
        acc[0][4] += xv0*w1.x; acc[0][5] += xv0*w1.y; acc[0][6] += xv0*w1.z; acc[0][7] += xv0*w1.w;
        acc[1][0] += xv1*w0.x; acc[1][1] += xv1*w0.y; acc[1][2] += xv1*w0.z; acc[1][3] += xv1*w0.w;
        acc[1][4] += xv1*w1.x; acc[1][5] += xv1*w1.y; acc[1][6] += xv1*w1.z; acc[1][7] += xv1*w1.w;
        acc[2][0] += xv2*w0.x; acc[2][1] += xv2*w0.y; acc[2][2] += xv2*w0.z; acc[2][3] += xv2*w0.w;
        acc[2][4] += xv2*w1.x; acc[2][5] += xv2*w1.y; acc[2][6] += xv2*w1.z; acc[2][7] += xv2*w1.w;
        acc[3][0] += xv3*w0.x; acc[3][1] += xv3*w0.y; acc[3][2] += xv3*w0.z; acc[3][3] += xv3*w0.w;
        acc[3][4] += xv3*w1.x; acc[3][5] += xv3*w1.y; acc[3][6] += xv3*w1.z; acc[3][7] += xv3*w1.w;
    }

    // Epilogue: write h, fused attention dots + 8-lane tree reduce
    const float4 u0  = ((const float4*)Wat)[tc*2];
    const float4 u1  = ((const float4*)Wat)[tc*2+1];
    const float4 v0  = ((const float4*)Wat)[16 + tc*2];
    const float4 v1  = ((const float4*)Wat)[16 + tc*2+1];
    const float  batv = bat[0];

    #pragma unroll
    for (int k = 0; k < 4; k++){
        int grow = tile*TILE + rl + k*32;
        float4* hp = (float4*)&hout[(size_t)grow*DOUT + tc*8];
        hp[0] = make_float4(acc[k][0], acc[k][1], acc[k][2], acc[k][3]);
        hp[1] = make_float4(acc[k][4], acc[k][5], acc[k][6], acc[k][7]);

        float pa1 = acc[k][0]*u0.x + acc[k][1]*u0.y + acc[k][2]*u0.z + acc[k][3]*u0.w
                  + acc[k][4]*u1.x + acc[k][5]*u1.y + acc[k][6]*u1.z + acc[k][7]*u1.w;
        float pa2 = acc[k][0]*v0.x + acc[k][1]*v0.y + acc[k][2]*v0.z + acc[k][3]*v0.w
                  + acc[k][4]*v1.x + acc[k][5]*v1.y + acc[k][6]*v1.z + acc[k][7]*v1.w;
        #pragma unroll
        for (int o = 4; o; o >>= 1){
            pa1 += __shfl_down_sync(0xffffffffu, pa1, o, 8);
            pa2 += __shfl_down_sync(0xffffffffu, pa2, o, 8);
        }
        if (tc == 0){
            g_a1[grow] = pa1 + batv;   // fold b_at here
            g_a2[grow] = pa2;
        }
    }
}

// ---- Kernel 2: 9-way gather + leaky_relu + softmax -> attn_weight ----
__global__ void attn_kernel(float* __restrict__ wout){
    int r = blockIdx.x*blockDim.x + threadIdx.x;
    if (r >= RTOT) return;
    int b  = r / NN;
    int n  = r - b*NN;
    int gr = n / GRID_N;
    int gc = n - gr*GRID_N;
    // reference clamps: row 0 shifted +1, row 24 shifted -1 (same for cols)
    int rb = gr + (gr == 0) - (gr == GRID_N-1);
    int cb = gc + (gc == 0) - (gc == GRID_N-1);

    float A = g_a1[r];
    const float* a2b = g_a2 + b*NN;

    float s[9];
    #pragma unroll
    for (int k = 0; k < 9; k++){
        int dr = k/3 - 1, dc = k%3 - 1;
        float v = A + a2b[(rb+dr)*GRID_N + (cb+dc)];
        s[k] = (v > 0.f) ? v : 0.01f*v;      // leaky_relu(0.01)
    }
    float m = s[0];
    #pragma unroll
    for (int k = 1; k < 9; k++) m = fmaxf(m, s[k]);
    float sum = 0.f;
    #pragma unroll
    for (int k = 0; k < 9; k++){ s[k] = __expf(s[k] - m); sum += s[k]; }
    float inv = 1.0f / sum;
    #pragma unroll
    for (int k = 0; k < 9; k++) wout[(size_t)r*9 + k] = s[k]*inv;
}

extern "C" void kernel_launch(void* const* d_in, const int* in_sizes, int n_in,
                              void* d_out, int out_size)
{
    const float* x   = (const float*)d_in[0];   // [512,625,66]
    const float* Wfc = (const float*)d_in[1];   // [64,66]
    const float* bfc = (const float*)d_in[2];   // [64]
    const float* Wat = (const float*)d_in[3];   // [1,128]
    const float* bat = (const float*)d_in[4];   // [1]
    float* out = (float*)d_out;
    // output layout: attn_vector [512,625,64] then attn_weight [512,625,9]
    float* hout = out;
    float* wout = out + (size_t)RTOT*DOUT;

    prep_kernel<<<(FIN*DOUT + 255)/256, 256>>>(Wfc);
    gemm_kernel<<<NTILES, THREADS>>>(x, bfc, Wat, bat, hout);
    attn_kernel<<<(RTOT + 255)/256, 256>>>(wout);
}

// round 16
// speedup vs baseline: 2.4066x; 1.4303x over previous
#include <cuda_runtime.h>
#include <cstdint>

#define GRID_N 25
#define NN 625
#define RTOT 320000          // 512*625 rows
#define FIN 66
#define DOUT 64
#define TILEM 128            // rows per CTA
#define NTILES (RTOT/TILEM)  // 2500
#define THREADS 128
#define KPAD 72              // 9 k-steps of 8
#define WSTR 65              // padded W smem stride (conflict-free B frags)

// dynamic smem layout (floats)
#define OFF_W    0                    // [72][65] = 4680
#define OFF_UV   4680                 // 128
#define OFF_BIAS 4808                 // 64
#define OFF_X    4872                 // 128*66 + 8 pad = 8456
#define SMEM_FLOATS (OFF_X + 8456)    // 13328 floats = 53312 B

// ---- device scratch ----
__device__ float g_Wt[KPAD*WSTR];  // B image: [k][n] f32, zero-padded
__device__ float g_a1[RTOT];
__device__ float g_a2[RTOT];

__device__ __forceinline__ uint32_t tf32hi(float x){
    uint32_t r; asm("cvt.rna.tf32.f32 %0, %1;" : "=r"(r) : "f"(x)); return r;
}
__device__ __forceinline__ void mma_tf32(float* d,
    uint32_t a0, uint32_t a1, uint32_t a2, uint32_t a3,
    uint32_t b0, uint32_t b1)
{
    asm volatile(
        "mma.sync.aligned.m16n8k8.row.col.f32.tf32.tf32.f32 "
        "{%0,%1,%2,%3}, {%4,%5,%6,%7}, {%8,%9}, {%0,%1,%2,%3};"
        : "+f"(d[0]), "+f"(d[1]), "+f"(d[2]), "+f"(d[3])
        : "r"(a0), "r"(a1), "r"(a2), "r"(a3), "r"(b0), "r"(b1));
}

// ---- Kernel 0: build padded W image g_Wt[k][n] = W_fc[n][k], zeros elsewhere ----
__global__ void prep_kernel(const float* __restrict__ Wfc){
    int i = blockIdx.x*blockDim.x + threadIdx.x;
    if (i >= KPAD*WSTR) return;
    int k = i / WSTR, n = i - k*WSTR;
    g_Wt[i] = (n < DOUT && k < FIN) ? Wfc[n*FIN + k] : 0.f;
}

// ---- Kernel 1: tf32-split MMA GEMM + fused epilogue ----
__global__ __launch_bounds__(THREADS)
void gemm_kernel(const float* __restrict__ x,
                 const float* __restrict__ bfc,
                 const float* __restrict__ Wat,
                 const float* __restrict__ bat,
                 float* __restrict__ hout)
{
    extern __shared__ float sm[];
    float* sW    = sm + OFF_W;
    float* sUV   = sm + OFF_UV;
    float* sBias = sm + OFF_BIAS;
    float* sX    = sm + OFF_X;

    const int tid  = threadIdx.x;
    const int warp = tid >> 5, lane = tid & 31;
    const int gid  = lane >> 2, tig = lane & 3;

    // Stage W image (18.7KB), params, x tile (33.8KB contiguous float4)
    for (int i = tid; i < KPAD*WSTR; i += THREADS) sW[i] = g_Wt[i];
    sUV[tid] = Wat[tid];                       // THREADS==128 exactly
    if (tid < DOUT) sBias[tid] = bfc[tid];
    {
        const float4* xg = (const float4*)(x + (size_t)blockIdx.x*(TILEM*FIN));
        float4* xs = (float4*)sX;
        #pragma unroll 4
        for (int i = tid; i < (TILEM*FIN)/4; i += THREADS) xs[i] = xg[i];
    }
    if (tid < 8) sX[TILEM*FIN + tid] = 0.f;    // zero tail: row127 k>=66 reads
    __syncthreads();

    float acc[16][4];                          // [mt*8+nt][4]
    #pragma unroll
    for (int t = 0; t < 16; t++){
        acc[t][0]=0.f; acc[t][1]=0.f; acc[t][2]=0.f; acc[t][3]=0.f;
    }

    const float* xw = sX + warp*32*FIN;        // this warp's 32 rows

    #pragma unroll
    for (int ks = 0; ks < 9; ks++){
        const int k0 = ks*8;
        uint32_t Ahi[2][4], Alo[2][4];
        #pragma unroll
        for (int mt = 0; mt < 2; mt++){
            const float* xr = xw + (mt*16 + gid)*FIN + k0 + tig;
            float a0 = xr[0];
            float a1 = xr[8*FIN];
            float a2 = xr[4];
            float a3 = xr[8*FIN + 4];
            Ahi[mt][0] = tf32hi(a0); Alo[mt][0] = tf32hi(a0 - __uint_as_float(Ahi[mt][0]));
            Ahi[mt][1] = tf32hi(a1); Alo[mt][1] = tf32hi(a1 - __uint_as_float(Ahi[mt][1]));
            Ahi[mt][2] = tf32hi(a2); Alo[mt][2] = tf32hi(a2 - __uint_as_float(Ahi[mt][2]));
            Ahi[mt][3] = tf32hi(a3); Alo[mt][3] = tf32hi(a3 - __uint_as_float(Ahi[mt][3]));
        }
        #pragma unroll
        for (int nt = 0; nt < 8; nt++){
            const float* wr = sW + (k0 + tig)*WSTR + nt*8 + gid;
            float b0 = wr[0];
            float b1 = wr[4*WSTR];
            uint32_t bh0 = tf32hi(b0), bh1 = tf32hi(b1);
            uint32_t bl0 = tf32hi(b0 - __uint_as_float(bh0));
            uint32_t bl1 = tf32hi(b1 - __uint_as_float(bh1));
            #pragma unroll
            for (int mt = 0; mt < 2; mt++){
                float* d = acc[mt*8 + nt];
                mma_tf32(d, Ahi[mt][0], Ahi[mt][1], Ahi[mt][2], Ahi[mt][3], bh0, bh1);
                mma_tf32(d, Ahi[mt][0], Ahi[mt][1], Ahi[mt][2], Ahi[mt][3], bl0, bl1);
                mma_tf32(d, Alo[mt][0], Alo[mt][1], Alo[mt][2], Alo[mt][3], bh0, bh1);
            }
        }
    }

    // Epilogue: bias, h write, fused a1/a2 dots (quad reduce)
    const float batv = bat[0];
    #pragma unroll
    for (int mt = 0; mt < 2; mt++){
        const int r0 = blockIdx.x*TILEM + warp*32 + mt*16 + gid;
        const int r1 = r0 + 8;
        float p1a = 0.f, p2a = 0.f, p1b = 0.f, p2b = 0.f;
        #pragma unroll
        for (int nt = 0; nt < 8; nt++){
            const int col = nt*8 + 2*tig;
            const float u0 = sUV[col],    u1 = sUV[col+1];
            const float v0 = sUV[64+col], v1 = sUV[64+col+1];
            const float bb0 = sBias[col], bb1 = sBias[col+1];
            const float* d = acc[mt*8 + nt];
            float c0 = d[0] + bb0, c1 = d[1] + bb1;   // row r0
            float c2 = d[2] + bb0, c3 = d[3] + bb1;   // row r1
            *(float2*)&hout[(size_t)r0*DOUT + col] = make_float2(c0, c1);
            *(float2*)&hout[(size_t)r1*DOUT + col] = make_float2(c2, c3);
            p1a += c0*u0 + c1*u1;  p2a += c0*v0 + c1*v1;
            p1b += c2*u0 + c3*u1;  p2b += c2*v0 + c3*v1;
        }
        #pragma unroll
        for (int o = 1; o <= 2; o <<= 1){
            p1a += __shfl_xor_sync(0xffffffffu, p1a, o);
            p2a += __shfl_xor_sync(0xffffffffu, p2a, o);
            p1b += __shfl_xor_sync(0xffffffffu, p1b, o);
            p2b += __shfl_xor_sync(0xffffffffu, p2b, o);
        }
        if (tig == 0){
            g_a1[r0] = p1a + batv;  g_a2[r0] = p2a;
            g_a1[r1] = p1b + batv;  g_a2[r1] = p2b;
        }
    }
}

// ---- Kernel 2: 9-way gather + leaky_relu + softmax -> attn_weight ----
__global__ void attn_kernel(float* __restrict__ wout){
    int r = blockIdx.x*blockDim.x + threadIdx.x;
    if (r >= RTOT) return;
    int b  = r / NN;
    int n  = r - b*NN;
    int gr = n / GRID_N;
    int gc = n - gr*GRID_N;
    int rb = gr + (gr == 0) - (gr == GRID_N-1);
    int cb = gc + (gc == 0) - (gc == GRID_N-1);

    float A = g_a1[r];
    const float* a2b = g_a2 + b*NN;

    float s[9];
    #pragma unroll
    for (int k = 0; k < 9; k++){
        int dr = k/3 - 1, dc = k%3 - 1;
        float v = A + a2b[(rb+dr)*GRID_N + (cb+dc)];
        s[k] = (v > 0.f) ? v : 0.01f*v;
    }
    float m = s[0];
    #pragma unroll
    for (int k = 1; k < 9; k++) m = fmaxf(m, s[k]);
    float sum = 0.f;
    #pragma unroll
    for (int k = 0; k < 9; k++){ s[k] = __expf(s[k] - m); sum += s[k]; }
    float inv = 1.0f / sum;
    #pragma unroll
    for (int k = 0; k < 9; k++) wout[(size_t)r*9 + k] = s[k]*inv;
}

extern "C" void kernel_launch(void* const* d_in, const int* in_sizes, int n_in,
                              void* d_out, int out_size)
{
    const float* x   = (const float*)d_in[0];   // [512,625,66]
    const float* Wfc = (const float*)d_in[1];   // [64,66]
    const float* bfc = (const float*)d_in[2];   // [64]
    const float* Wat = (const float*)d_in[3];   // [1,128]
    const float* bat = (const float*)d_in[4];   // [1]
    float* out  = (float*)d_out;
    float* hout = out;                          // attn_vector [512,625,64]
    float* wout = out + (size_t)RTOT*DOUT;      // attn_weight [512,625,9]

    static int smem_set = 0;
    if (!smem_set){
        cudaFuncSetAttribute(gemm_kernel, cudaFuncAttributeMaxDynamicSharedMemorySize,
                             SMEM_FLOATS*4);
        smem_set = 1;
    }

    prep_kernel<<<(KPAD*WSTR + 255)/256, 256>>>(Wfc);
    gemm_kernel<<<NTILES, THREADS, SMEM_FLOATS*4>>>(x, bfc, Wat, bat, hout);
    attn_kernel<<<(RTOT + 255)/256, 256>>>(wout);
}